// round 12
// baseline (speedup 1.0000x reference)
#include <cuda_runtime.h>
#include <math.h>

#define HDIM 64
#define VOCAB 50000
#define NTD 8192
#define NBU 8191
#define LBU 4096
#define WSTR 68     // padded stride for weight matrices in shared
#define GRID 296    // 2 blocks per SM, all co-resident
#define NTT 1564    // transpose tiles: 782 per table

// ---------------- device scratch (static allocations only) ----------------
__device__ float g_ET_td[(size_t)VOCAB * HDIM];   // E transposed: (V, H)
__device__ float g_ET_bu[(size_t)VOCAB * HDIM];
__device__ float g_zx_td[NTD * HDIM];
__device__ float g_rx_td[NTD * HDIM];
__device__ float g_hx_td[NTD * HDIM];
__device__ float g_zx_bu[NBU * HDIM];
__device__ float g_rx_bu[NBU * HDIM];
__device__ float g_hx_bu[NBU * HDIM];
__device__ float g_h_td[(NTD + 1) * HDIM];
__device__ float g_h_bu[NBU * HDIM];
__device__ float g_tdmax[64 * HDIM];
// g_ctr: [0]=transpose bar, [1]=embed bar, [2]=td join, [3..11]=td levels 5..13,
//        [12]=head (65), [13..19]=bu levels 1..7, [20]=final (GRID), [22],[23]=work queues
__device__ int g_ctr[32];   // zero-initialized at load; self-reset at kernel end

// ---------------- fast activations (ex2/rcp approx; abs err ~1e-6) ----------------
__device__ __forceinline__ float fex2(float x) { float r; asm("ex2.approx.f32 %0,%1;" : "=f"(r) : "f"(x)); return r; }
__device__ __forceinline__ float frcp(float x) { float r; asm("rcp.approx.f32 %0,%1;" : "=f"(r) : "f"(x)); return r; }
__device__ __forceinline__ float sigmf(float x) { return frcp(1.0f + fex2(-1.4426950408889634f * x)); }
__device__ __forceinline__ float tanhf_fast(float x) { return 2.0f * sigmf(2.0f * x) - 1.0f; }

// global barrier on g_ctr[idx]: arrive (release); optionally spin to target (acquire)
__device__ __forceinline__ void gbar(int idx, int target, bool wait) {
    __syncthreads();
    if (threadIdx.x == 0) {
        unsigned long long g;
        asm volatile("cvta.to.global.u64 %0, %1;" : "=l"(g) : "l"(&g_ctr[idx]));
        asm volatile("red.release.gpu.global.add.u32 [%0], 1;" :: "l"(g) : "memory");
        if (wait) {
            int v;
            do {
                asm volatile("ld.acquire.gpu.global.u32 %0, [%1];" : "=r"(v) : "l"(g) : "memory");
            } while (v < target);
        }
    }
    __syncthreads();
}

// ---------------- GRU for one 16-node tile (all 256 threads participate) ----------------
__device__ __forceinline__ void gru_tile(
    bool is_td, int lo, int cnt, int tile,
    const float* __restrict__ gz, const float* __restrict__ gr, const float* __restrict__ gh,
    const float* sU, float* sHp, float* sHr, int slot, int h4,
    bool useP, float4 paz, float4 par, float4 pah)
{
    int r = tile * 16 + slot;
    bool act = (r < cnt);
    float4 hp = make_float4(0.f, 0.f, 0.f, 0.f);
    float4 az, ar, ah;
    int outRow = 0;
    if (act) {
        int gi;
        if (is_td) {
            int o = lo + r;
            gi = o - 1;
            hp = *(const float4*)&g_h_td[((o - 1) >> 1) * 64 + h4];
            outRow = o;
        } else {
            int j = lo + r;
            gi = LBU + j;
            float4 a = *(const float4*)&g_h_bu[(2 * j) * 64 + h4];
            float4 b = *(const float4*)&g_h_bu[(2 * j + 1) * 64 + h4];
            hp = make_float4(a.x + b.x, a.y + b.y, a.z + b.z, a.w + b.w);
            outRow = gi;
        }
        if (useP) { az = paz; ar = par; ah = pah; }
        else {
            az = *(const float4*)&gz[gi * 64 + h4];
            ar = *(const float4*)&gr[gi * 64 + h4];
            ah = *(const float4*)&gh[gi * 64 + h4];
        }
    }
    *(float4*)&sHp[slot * 64 + h4] = hp;
    __syncthreads();
    float4 z = make_float4(0, 0, 0, 0), rr = make_float4(0, 0, 0, 0);
    if (act) {
        float4 mz = az, mr = ar;
        const float* hpv = &sHp[slot * 64];
#pragma unroll 4
        for (int k = 0; k < 64; k++) {
            float x = hpv[k];
            float4 uz4 = *(const float4*)&sU[0 * 64 * WSTR + k * WSTR + h4];
            float4 ur4 = *(const float4*)&sU[1 * 64 * WSTR + k * WSTR + h4];
            mz.x += uz4.x * x; mz.y += uz4.y * x; mz.z += uz4.z * x; mz.w += uz4.w * x;
            mr.x += ur4.x * x; mr.y += ur4.y * x; mr.z += ur4.z * x; mr.w += ur4.w * x;
        }
        z = make_float4(sigmf(mz.x), sigmf(mz.y), sigmf(mz.z), sigmf(mz.w));
        rr = make_float4(sigmf(mr.x), sigmf(mr.y), sigmf(mr.z), sigmf(mr.w));
    }
    float4 hr = make_float4(hp.x * rr.x, hp.y * rr.y, hp.z * rr.z, hp.w * rr.w);
    *(float4*)&sHr[slot * 64 + h4] = act ? hr : make_float4(0, 0, 0, 0);
    __syncthreads();
    if (act) {
        float4 mh = ah;
        const float* hrv = &sHr[slot * 64];
#pragma unroll 4
        for (int k = 0; k < 64; k++) {
            float x = hrv[k];
            float4 uh4 = *(const float4*)&sU[2 * 64 * WSTR + k * WSTR + h4];
            mh.x += uh4.x * x; mh.y += uh4.y * x; mh.z += uh4.z * x; mh.w += uh4.w * x;
        }
        float4 c = make_float4(tanhf_fast(mh.x), tanhf_fast(mh.y), tanhf_fast(mh.z), tanhf_fast(mh.w));
        float4 hn;
        hn.x = z.x * hp.x + (1.f - z.x) * c.x;
        hn.y = z.y * hp.y + (1.f - z.y) * c.y;
        hn.z = z.z * hp.z + (1.f - z.z) * c.z;
        hn.w = z.w * hp.w + (1.f - z.w) * c.w;
        if (is_td) *(float4*)&g_h_td[outRow * 64 + h4] = hn;
        else       *(float4*)&g_h_bu[outRow * 64 + h4] = hn;
    }
    __syncthreads();
}

// ---------------- THE kernel: transpose -> embed -> tree -> head ----------------
__global__ void __launch_bounds__(256, 2) k_mega(
    const float* __restrict__ E_td, const float* __restrict__ E_bu,
    const float* __restrict__ td_word, const int* __restrict__ td_idx,
    const float* __restrict__ bu_word, const int* __restrict__ bu_idx,
    const float* __restrict__ Wz_td, const float* __restrict__ Wr_td, const float* __restrict__ Wh_td,
    const float* __restrict__ bz_td, const float* __restrict__ br_td, const float* __restrict__ bh_td,
    const float* __restrict__ Wz_bu, const float* __restrict__ Wr_bu, const float* __restrict__ Wh_bu,
    const float* __restrict__ bz_bu, const float* __restrict__ br_bu, const float* __restrict__ bh_bu,
    const float* __restrict__ Uz_td, const float* __restrict__ Ur_td, const float* __restrict__ Uh_td,
    const float* __restrict__ Uz_bu, const float* __restrict__ Ur_bu, const float* __restrict__ Uh_bu,
    const float* __restrict__ W1, const float* __restrict__ b1,
    const float* __restrict__ W4, const float* __restrict__ b4,
    float* __restrict__ out)
{
    extern __shared__ float sm[];
    int bid = blockIdx.x;
    int tid = threadIdx.x;

    // ============ phase 1: transpose E (H,V) -> ET (V,H) ============
    {
        float (*tile)[65] = (float (*)[65])sm;
        if (bid == 0 && tid < 64) g_h_td[tid] = 0.f;     // node_h[0] = 0
        for (int ti = bid; ti < NTT; ti += GRID) {
            const float* E = (ti < 782) ? E_td : E_bu;
            float* ET = (ti < 782) ? g_ET_td : g_ET_bu;
            int v0 = ((ti < 782) ? ti : ti - 782) * 64;
            int rem = VOCAB - v0;                         // 64 normally, 16 for last tile
            __syncthreads();
#pragma unroll
            for (int it = 0; it < 4; it++) {
                int e = it * 256 + tid;
                int h = e >> 4, c = (e & 15) * 4;
                if (c < rem) {
                    float4 v = *(const float4*)&E[(size_t)h * VOCAB + v0 + c];
                    tile[h][c] = v.x; tile[h][c + 1] = v.y;
                    tile[h][c + 2] = v.z; tile[h][c + 3] = v.w;
                }
            }
            __syncthreads();
#pragma unroll
            for (int it = 0; it < 4; it++) {
                int e = it * 256 + tid;
                int v = e >> 4, c = (e & 15) * 4;
                if (v < rem) {
                    float4 val = make_float4(tile[c][v], tile[c + 1][v], tile[c + 2][v], tile[c + 3][v]);
                    *(float4*)&ET[(size_t)(v0 + v) * 64 + c] = val;
                }
            }
        }
    }
    gbar(0, GRID, true);

    // ============ phase 2: embedding gather + gate pre-activations ============
    {
        float* sW = sm;                       // 3 * 64 * WSTR
        float* sb = sW + 3 * 64 * WSTR;       // 192
        float* sWord = sb + 192;              // 32 * 64
        float* sXe = sWord + 2048;            // 32 * 64
        int* sIdx = (int*)(sXe + 2048);       // 32 * 64
        __shared__ int sChunk;

        bool is_td = (bid < 148);
        const float* word = is_td ? td_word : bu_word;
        const int* idx = is_td ? td_idx : bu_idx;
        const float* ET = is_td ? g_ET_td : g_ET_bu;
        const float* Wz = is_td ? Wz_td : Wz_bu;
        const float* Wr = is_td ? Wr_td : Wr_bu;
        const float* Wh = is_td ? Wh_td : Wh_bu;
        const float* bz = is_td ? bz_td : bz_bu;
        const float* br = is_td ? br_td : br_bu;
        const float* bh = is_td ? bh_td : bh_bu;
        float* zx = is_td ? g_zx_td : g_zx_bu;
        float* rx = is_td ? g_rx_td : g_rx_bu;
        float* hx = is_td ? g_hx_td : g_hx_bu;
        int nNodes = is_td ? NTD : NBU;
        int qIdx = is_td ? 22 : 23;

        for (int g = 0; g < 3; g++) {
            const float* Wg = (g == 0) ? Wz : (g == 1) ? Wr : Wh;
            for (int e = tid; e < 4096; e += 256) {
                int hh = e >> 6, kk = e & 63;
                sW[g * 64 * WSTR + kk * WSTR + hh] = Wg[e];
            }
        }
        if (tid < 64) sb[tid] = bz[tid];
        else if (tid < 128) sb[tid] = br[tid - 64];
        else if (tid < 192) sb[tid] = bh[tid - 128];

        // software-pipelined chunk queue: pop next ticket while processing current
        if (tid == 0) sChunk = atomicAdd(&g_ctr[qIdx], 1);
        __syncthreads();

        int slot = tid >> 4;
        int t = tid & 15;
        int h4 = t * 4;

        for (;;) {
            int c = sChunk;
            if (c >= 256) break;
            __syncthreads();                 // sChunk consumed by all; safe to repop
            if (tid == 0) sChunk = atomicAdd(&g_ctr[qIdx], 1);
            int base = c * 32;
            int n0 = base + slot;
            int n1 = base + slot + 16;
            bool full = (base + 32 <= nNodes);
            bool a0 = full || (n0 < nNodes);
            bool a1 = full || (n1 < nNodes);
            if (a0) {
                *(int4*)&sIdx[slot * 64 + h4] = *(const int4*)&idx[n0 * 64 + h4];
                *(float4*)&sWord[slot * 64 + h4] = *(const float4*)&word[n0 * 64 + h4];
            }
            if (a1) {
                *(int4*)&sIdx[(slot + 16) * 64 + h4] = *(const int4*)&idx[n1 * 64 + h4];
                *(float4*)&sWord[(slot + 16) * 64 + h4] = *(const float4*)&word[n1 * 64 + h4];
            }
            __syncthreads();
            float4 acc0 = make_float4(0.f, 0.f, 0.f, 0.f);
            float4 acc1 = make_float4(0.f, 0.f, 0.f, 0.f);
            {
                const int* ip0 = &sIdx[slot * 64];
                const float* wp0 = &sWord[slot * 64];
                const int* ip1 = &sIdx[(slot + 16) * 64];
                const float* wp1 = &sWord[(slot + 16) * 64];
                if (full) {
#pragma unroll 8
                    for (int w = 0; w < 64; w++) {
                        float4 ea = *(const float4*)&ET[ip0[w] * 64 + h4];
                        float4 eb = *(const float4*)&ET[ip1[w] * 64 + h4];
                        float wa = wp0[w], wb = wp1[w];
                        acc0.x += ea.x * wa; acc0.y += ea.y * wa; acc0.z += ea.z * wa; acc0.w += ea.w * wa;
                        acc1.x += eb.x * wb; acc1.y += eb.y * wb; acc1.z += eb.z * wb; acc1.w += eb.w * wb;
                    }
                } else {
#pragma unroll 4
                    for (int w = 0; w < 64; w++) {
                        if (a0) {
                            float4 ea = *(const float4*)&ET[ip0[w] * 64 + h4];
                            float wa = wp0[w];
                            acc0.x += ea.x * wa; acc0.y += ea.y * wa; acc0.z += ea.z * wa; acc0.w += ea.w * wa;
                        }
                        if (a1) {
                            float4 eb = *(const float4*)&ET[ip1[w] * 64 + h4];
                            float wb = wp1[w];
                            acc1.x += eb.x * wb; acc1.y += eb.y * wb; acc1.z += eb.z * wb; acc1.w += eb.w * wb;
                        }
                    }
                }
            }
            *(float4*)&sXe[slot * 64 + h4] = acc0;
            *(float4*)&sXe[(slot + 16) * 64 + h4] = acc1;
            __syncthreads();
            {
                const float* xe0 = &sXe[slot * 64];
                const float* xe1 = &sXe[(slot + 16) * 64];
                float4 bzv = *(const float4*)&sb[0 * 64 + h4];
                float4 brv = *(const float4*)&sb[1 * 64 + h4];
                float4 bhv = *(const float4*)&sb[2 * 64 + h4];
                float4 az0 = bzv, ar0 = brv, ah0 = bhv;
                float4 az1 = bzv, ar1 = brv, ah1 = bhv;
#pragma unroll 4
                for (int k = 0; k < 64; k++) {
                    float4 wz4 = *(const float4*)&sW[0 * 64 * WSTR + k * WSTR + h4];
                    float4 wr4 = *(const float4*)&sW[1 * 64 * WSTR + k * WSTR + h4];
                    float4 wh4 = *(const float4*)&sW[2 * 64 * WSTR + k * WSTR + h4];
                    float x0 = xe0[k], x1 = xe1[k];
                    az0.x += wz4.x * x0; az0.y += wz4.y * x0; az0.z += wz4.z * x0; az0.w += wz4.w * x0;
                    ar0.x += wr4.x * x0; ar0.y += wr4.y * x0; ar0.z += wr4.z * x0; ar0.w += wr4.w * x0;
                    ah0.x += wh4.x * x0; ah0.y += wh4.y * x0; ah0.z += wh4.z * x0; ah0.w += wh4.w * x0;
                    az1.x += wz4.x * x1; az1.y += wz4.y * x1; az1.z += wz4.z * x1; az1.w += wz4.w * x1;
                    ar1.x += wr4.x * x1; ar1.y += wr4.y * x1; ar1.z += wr4.z * x1; ar1.w += wr4.w * x1;
                    ah1.x += wh4.x * x1; ah1.y += wh4.y * x1; ah1.z += wh4.z * x1; ah1.w += wh4.w * x1;
                }
#pragma unroll
                for (int p = 0; p < 2; p++) {
                    int n = p ? n1 : n0;
                    bool act = p ? a1 : a0;
                    float4 az = p ? az1 : az0, ar = p ? ar1 : ar0, ah = p ? ah1 : ah0;
                    if (!act) continue;
                    if (is_td || n >= LBU) {
                        *(float4*)&zx[n * 64 + h4] = az;
                        *(float4*)&rx[n * 64 + h4] = ar;
                        *(float4*)&hx[n * 64 + h4] = ah;
                    } else {
                        float4 lh;
                        lh.x = (1.f - sigmf(az.x)) * tanhf_fast(ah.x);
                        lh.y = (1.f - sigmf(az.y)) * tanhf_fast(ah.y);
                        lh.z = (1.f - sigmf(az.z)) * tanhf_fast(ah.z);
                        lh.w = (1.f - sigmf(az.w)) * tanhf_fast(ah.w);
                        *(float4*)&g_h_bu[n * 64 + h4] = lh;
                    }
                }
            }
            __syncthreads();
        }
    }
    gbar(1, GRID, bid < 128);

    // ============ phase 3: tree recurrences + head ============
    if (bid < 128) {
        float* sU = sm;                       // 3 * 64 * WSTR
        float* sHp = sU + 3 * 64 * WSTR;      // 16 * 64
        float* sHr = sHp + 1024;              // 16 * 64

        bool is_td = (bid < 64);
        int gid = is_td ? bid : bid - 64;

        const float* Uz = is_td ? Uz_td : Uz_bu;
        const float* Ur = is_td ? Ur_td : Ur_bu;
        const float* Uh = is_td ? Uh_td : Uh_bu;
        const float* gz = is_td ? g_zx_td : g_zx_bu;
        const float* gr = is_td ? g_rx_td : g_rx_bu;
        const float* gh = is_td ? g_hx_td : g_hx_bu;

        for (int g = 0; g < 3; g++) {
            const float* Ug = (g == 0) ? Uz : (g == 1) ? Ur : Uh;
            for (int e = tid; e < 4096; e += 256) {
                int hh = e >> 6, kk = e & 63;
                sU[g * 64 * WSTR + kk * WSTR + hh] = Ug[e];
            }
        }
        if (bid == 0) {
            // prefetch head weights into L2 (used ~tree-latency later)
            asm volatile("prefetch.global.L2 [%0];" :: "l"(&W1[tid * 32]));
            if (tid < 8) asm volatile("prefetch.global.L2 [%0];" :: "l"(&W4[tid * 32]));
        }
        __syncthreads();

        int slot = tid >> 4;
        int t = tid & 15;
        int h4 = t * 4;
        const float4 f40 = make_float4(0.f, 0.f, 0.f, 0.f);

        if (is_td) {
            // levels 1..4 (2..16 nodes, 1 tile each): solo by block 0
            if (gid == 0) {
                for (int s = 1; s <= 4; s++) {
                    int lo = (1 << s) - 1, cnt = 1 << s;
                    gru_tile(true, lo, cnt, 0, gz, gr, gh, sU, sHp, sHr, slot, h4, false, f40, f40, f40);
                }
            }
            // prefetch level-5 gates (cnt=32, lo=31)
            float4 paz = f40, par = f40, pah = f40;
            bool useP = false;
            {
                int r = gid * 16 + slot;
                if (r < 32) {
                    int gi = 30 + r;
                    paz = *(const float4*)&gz[gi * 64 + h4];
                    par = *(const float4*)&gr[gi * 64 + h4];
                    pah = *(const float4*)&gh[gi * 64 + h4];
                    useP = true;
                }
            }
            gbar(2, 64, true);
            // levels 5..13: 64 blocks, per-level barrier, gate prefetch across barrier
            for (int s = 5; s <= 13; s++) {
                int lo = (1 << s) - 1;
                int cnt = (s < 13) ? (1 << s) : 2;
                int tiles = (cnt + 15) >> 4;
                for (int tile = gid; tile < tiles; tile += 64)
                    gru_tile(true, lo, cnt, tile, gz, gr, gh, sU, sHp, sHr, slot, h4,
                             (tile == gid) && useP, paz, par, pah);
                useP = false;
                if (s < 13) {
                    int s2 = s + 1;
                    int lo2 = (1 << s2) - 1;
                    int cnt2 = (s2 < 13) ? (1 << s2) : 2;
                    int r = gid * 16 + slot;
                    if (r < cnt2) {
                        int gi = lo2 + r - 1;
                        paz = *(const float4*)&gz[gi * 64 + h4];
                        par = *(const float4*)&gr[gi * 64 + h4];
                        pah = *(const float4*)&gh[gi * 64 + h4];
                        useP = true;
                    }
                }
                gbar(3 + s - 5, 64, true);
            }
            // partial max over leaf rows 4096..8192
            if (tid < 64) {
                int h = tid;
                float m = -1e30f;
                for (int r = 4096 + gid; r <= NTD; r += 64)
                    m = fmaxf(m, g_h_td[r * 64 + h]);
                g_tdmax[gid * 64 + h] = m;
            }
            // head barrier: 64 td + bu block 0 = 65; only td block 0 waits
            gbar(12, 65, gid == 0);

            if (gid == 0) {
                __shared__ float fs[128], f1[64], lg[4];
                if (tid < 64) {
                    float m = -1e30f;
#pragma unroll 8
                    for (int b = 0; b < 64; b++) m = fmaxf(m, g_tdmax[b * 64 + tid]);
                    fs[tid] = m;
                } else if (tid < 128) {
                    fs[tid] = g_h_bu[(NBU - 1) * 64 + (tid - 64)];
                }
                __syncthreads();
                {
                    int row = tid >> 2, part = tid & 3;
                    float s = 0.f;
#pragma unroll
                    for (int i = 0; i < 8; i++) {
                        int k = part * 32 + i * 4;
                        float4 w = *(const float4*)&W1[row * 128 + k];
                        s += w.x * fs[k] + w.y * fs[k + 1] + w.z * fs[k + 2] + w.w * fs[k + 3];
                    }
                    s += __shfl_down_sync(0xffffffffu, s, 1);
                    s += __shfl_down_sync(0xffffffffu, s, 2);
                    if (part == 0) f1[row] = fmaxf(s + b1[row], 0.f);
                }
                __syncthreads();
                if (tid < 128) {
                    int row = tid >> 5, lane = tid & 31;
                    float s = W4[row * 64 + lane] * f1[lane] + W4[row * 64 + 32 + lane] * f1[32 + lane];
#pragma unroll
                    for (int o = 16; o > 0; o >>= 1) s += __shfl_down_sync(0xffffffffu, s, o);
                    if (lane == 0) lg[row] = s + b4[row];
                }
                __syncthreads();
                if (tid == 0) {
                    float mx = fmaxf(fmaxf(lg[0], lg[1]), fmaxf(lg[2], lg[3]));
                    float e0 = expf(lg[0] - mx), e1 = expf(lg[1] - mx);
                    float e2 = expf(lg[2] - mx), e3 = expf(lg[3] - mx);
                    float sI = e0 + e1 + e2 + e3;
                    out[0] = e0 / sI; out[1] = e1 / sI; out[2] = e2 / sI; out[3] = e3 / sI;
                }
            }
        } else {
            // bu levels 1..7 (2048..32 nodes): 64 blocks, per-level barrier + prefetch
            float4 paz = f40, par = f40, pah = f40;
            bool useP = false;
            {
                int r = gid * 16 + slot;          // level 1: lo=0, cnt=2048
                if (r < 2048) {
                    int gi = LBU + r;
                    paz = *(const float4*)&gz[gi * 64 + h4];
                    par = *(const float4*)&gr[gi * 64 + h4];
                    pah = *(const float4*)&gh[gi * 64 + h4];
                    useP = true;
                }
            }
            for (int s = 1; s <= 7; s++) {
                int cnt = 1 << (12 - s);
                int lo = 4096 - (1 << (13 - s));
                int tiles = cnt >> 4;
                for (int tile = gid; tile < tiles; tile += 64)
                    gru_tile(false, lo, cnt, tile, gz, gr, gh, sU, sHp, sHr, slot, h4,
                             (tile == gid) && useP, paz, par, pah);
                useP = false;
                {
                    int s2 = s + 1;
                    int cnt2 = 1 << (12 - s2);
                    int lo2 = 4096 - (1 << (13 - s2));
                    int r = gid * 16 + slot;
                    if (r < cnt2) {
                        int gi = LBU + lo2 + r;
                        paz = *(const float4*)&gz[gi * 64 + h4];
                        par = *(const float4*)&gr[gi * 64 + h4];
                        pah = *(const float4*)&gh[gi * 64 + h4];
                        useP = true;
                    }
                }
                gbar(13 + s - 1, 64, true);
            }
            // levels 8..12 (16..1 nodes): solo by bu block 0
            if (gid == 0) {
                for (int s = 8; s <= 12; s++) {
                    int cnt = 1 << (12 - s);
                    int lo = 4096 - (1 << (13 - s));
                    gru_tile(false, lo, cnt, 0, gz, gr, gh, sU, sHp, sHr, slot, h4,
                             (s == 8) && useP, paz, par, pah);
                }
                gbar(12, 65, false);   // arrive at head barrier (publishes bu root)
            }
        }
    }

    // ============ final barrier + counter reset ============
    gbar(20, GRID, bid == 0);
    if (bid == 0 && tid < 32) g_ctr[tid] = 0;
}

// ---------------- launch ----------------
extern "C" void kernel_launch(void* const* d_in, const int* in_sizes, int n_in,
                              void* d_out, int out_size) {
    const float* td_x_word = (const float*)d_in[0];
    const float* bu_x_word = (const float*)d_in[1];
    const float* E_td  = (const float*)d_in[2];
    const float* Wz_td = (const float*)d_in[3];
    const float* Uz_td = (const float*)d_in[4];
    const float* bz_td = (const float*)d_in[5];
    const float* Wr_td = (const float*)d_in[6];
    const float* Ur_td = (const float*)d_in[7];
    const float* br_td = (const float*)d_in[8];
    const float* Wh_td = (const float*)d_in[9];
    const float* Uh_td = (const float*)d_in[10];
    const float* bh_td = (const float*)d_in[11];
    const float* E_bu  = (const float*)d_in[12];
    const float* Wz_bu = (const float*)d_in[13];
    const float* Uz_bu = (const float*)d_in[14];
    const float* bz_bu = (const float*)d_in[15];
    const float* Wr_bu = (const float*)d_in[16];
    const float* Ur_bu = (const float*)d_in[17];
    const float* br_bu = (const float*)d_in[18];
    const float* Wh_bu = (const float*)d_in[19];
    const float* Uh_bu = (const float*)d_in[20];
    const float* bh_bu = (const float*)d_in[21];
    const float* W1 = (const float*)d_in[22];
    const float* b1 = (const float*)d_in[23];
    const float* W4 = (const float*)d_in[24];
    const float* b4 = (const float*)d_in[25];

    const int* idx_td = (const int*)d_in[26];
    const int* idx_bu = (const int*)d_in[27];
    for (int i = 26; i < n_in; i++) {
        if (in_sizes[i] == NTD * 64) idx_td = (const int*)d_in[i];
        else if (in_sizes[i] == NBU * 64) idx_bu = (const int*)d_in[i];
    }

    const int smemM = (3 * 64 * WSTR + 192 + 2048 + 2048 + 2048) * 4;   // 77568 B
    cudaFuncSetAttribute(k_mega, cudaFuncAttributeMaxDynamicSharedMemorySize, smemM);

    k_mega<<<GRID, 256, smemM>>>(
        E_td, E_bu, td_x_word, idx_td, bu_x_word, idx_bu,
        Wz_td, Wr_td, Wh_td, bz_td, br_td, bh_td,
        Wz_bu, Wr_bu, Wh_bu, bz_bu, br_bu, bh_bu,
        Uz_td, Ur_td, Uh_td, Uz_bu, Ur_bu, Uh_bu,
        W1, b1, W4, b4, (float*)d_out);
}

// round 15
// speedup vs baseline: 1.6427x; 1.6427x over previous
#include <cuda_runtime.h>
#include <math.h>

#define HDIM 64
#define VOCAB 50000
#define NTD 8192
#define NBU 8191
#define LBU 4096
#define WSTR 68     // padded stride for weight matrices in shared
#define GRID 296    // 2 blocks per SM, all co-resident
#define NTT 1564    // transpose tiles: 782 per table
#define TDB 192     // td-chain tree blocks
#define BUB 104     // bu-chain tree blocks

// ---------------- device scratch (static allocations only) ----------------
__device__ float g_ET_td[(size_t)VOCAB * HDIM];   // E transposed: (V, H)
__device__ float g_ET_bu[(size_t)VOCAB * HDIM];
__device__ float g_zx_td[NTD * HDIM];
__device__ float g_rx_td[NTD * HDIM];
__device__ float g_hx_td[NTD * HDIM];
__device__ float g_zx_bu[NBU * HDIM];
__device__ float g_rx_bu[NBU * HDIM];
__device__ float g_hx_bu[NBU * HDIM];
__device__ float g_h_td[(NTD + 1) * HDIM];
__device__ float g_h_bu[NBU * HDIM];
__device__ float g_tdmax[64 * HDIM];
// barrier counters, padded to 32B each (idx*8). idx: [0]=transpose(296), [1]=embed(296),
// [2]=td join(192), [3..11]=td levels 5..13(192), [12]=head(193), [13..19]=bu levels 1..7(104),
// [20]=final(296)
__device__ int g_ctr[32 * 8];   // zero-initialized at load; self-reset at kernel end

// ---------------- fast activations (ex2/rcp approx; abs err ~1e-6) ----------------
__device__ __forceinline__ float fex2(float x) { float r; asm("ex2.approx.f32 %0,%1;" : "=f"(r) : "f"(x)); return r; }
__device__ __forceinline__ float frcp(float x) { float r; asm("rcp.approx.f32 %0,%1;" : "=f"(r) : "f"(x)); return r; }
__device__ __forceinline__ float sigmf(float x) { return frcp(1.0f + fex2(-1.4426950408889634f * x)); }
__device__ __forceinline__ float tanhf_fast(float x) { return 2.0f * sigmf(2.0f * x) - 1.0f; }

// global barrier on counter idx: arrive (release); optionally spin to target (acquire)
__device__ __forceinline__ void gbar(int idx, int target, bool wait) {
    __syncthreads();
    if (threadIdx.x == 0) {
        unsigned long long g;
        asm volatile("cvta.to.global.u64 %0, %1;" : "=l"(g) : "l"(&g_ctr[idx * 8]));
        asm volatile("red.release.gpu.global.add.u32 [%0], 1;" :: "l"(g) : "memory");
        if (wait) {
            int v;
            do {
                asm volatile("ld.acquire.gpu.global.u32 %0, [%1];" : "=r"(v) : "l"(g) : "memory");
            } while (v < target);
        }
    }
    __syncthreads();
}

// ---------------- GRU for one 16-node tile ----------------
// shared regions are half-warp-private -> __syncwarp only; warps flow independently.
__device__ __forceinline__ void gru_tile(
    bool is_td, int lo, int cnt, int tile,
    const float* __restrict__ gz, const float* __restrict__ gr, const float* __restrict__ gh,
    const float* sU, float* sHp, float* sHr, int slot, int h4,
    bool useP, float4 paz, float4 par, float4 pah)
{
    int r = tile * 16 + slot;
    bool act = (r < cnt);
    float4 hp = make_float4(0.f, 0.f, 0.f, 0.f);
    float4 az, ar, ah;
    int outRow = 0;
    if (act) {
        int gi;
        if (is_td) {
            int o = lo + r;
            gi = o - 1;
            hp = *(const float4*)&g_h_td[((o - 1) >> 1) * 64 + h4];
            outRow = o;
        } else {
            int j = lo + r;
            gi = LBU + j;
            float4 a = *(const float4*)&g_h_bu[(2 * j) * 64 + h4];
            float4 b = *(const float4*)&g_h_bu[(2 * j + 1) * 64 + h4];
            hp = make_float4(a.x + b.x, a.y + b.y, a.z + b.z, a.w + b.w);
            outRow = gi;
        }
        if (useP) { az = paz; ar = par; ah = pah; }
        else {
            az = *(const float4*)&gz[gi * 64 + h4];
            ar = *(const float4*)&gr[gi * 64 + h4];
            ah = *(const float4*)&gh[gi * 64 + h4];
        }
    }
    *(float4*)&sHp[slot * 64 + h4] = hp;
    __syncwarp();
    float4 z = make_float4(0, 0, 0, 0), rr = make_float4(0, 0, 0, 0);
    if (act) {
        float4 mz = az, mr = ar;
        const float* hpv = &sHp[slot * 64];
#pragma unroll 4
        for (int k = 0; k < 64; k++) {
            float x = hpv[k];
            float4 uz4 = *(const float4*)&sU[0 * 64 * WSTR + k * WSTR + h4];
            float4 ur4 = *(const float4*)&sU[1 * 64 * WSTR + k * WSTR + h4];
            mz.x += uz4.x * x; mz.y += uz4.y * x; mz.z += uz4.z * x; mz.w += uz4.w * x;
            mr.x += ur4.x * x; mr.y += ur4.y * x; mr.z += ur4.z * x; mr.w += ur4.w * x;
        }
        z = make_float4(sigmf(mz.x), sigmf(mz.y), sigmf(mz.z), sigmf(mz.w));
        rr = make_float4(sigmf(mr.x), sigmf(mr.y), sigmf(mr.z), sigmf(mr.w));
    }
    float4 hr = make_float4(hp.x * rr.x, hp.y * rr.y, hp.z * rr.z, hp.w * rr.w);
    *(float4*)&sHr[slot * 64 + h4] = act ? hr : make_float4(0, 0, 0, 0);
    __syncwarp();
    if (act) {
        float4 mh = ah;
        const float* hrv = &sHr[slot * 64];
#pragma unroll 4
        for (int k = 0; k < 64; k++) {
            float x = hrv[k];
            float4 uh4 = *(const float4*)&sU[2 * 64 * WSTR + k * WSTR + h4];
            mh.x += uh4.x * x; mh.y += uh4.y * x; mh.z += uh4.z * x; mh.w += uh4.w * x;
        }
        float4 c = make_float4(tanhf_fast(mh.x), tanhf_fast(mh.y), tanhf_fast(mh.z), tanhf_fast(mh.w));
        float4 hn;
        hn.x = z.x * hp.x + (1.f - z.x) * c.x;
        hn.y = z.y * hp.y + (1.f - z.y) * c.y;
        hn.z = z.z * hp.z + (1.f - z.z) * c.z;
        hn.w = z.w * hp.w + (1.f - z.w) * c.w;
        if (is_td) *(float4*)&g_h_td[outRow * 64 + h4] = hn;
        else       *(float4*)&g_h_bu[outRow * 64 + h4] = hn;
    }
    __syncwarp();
}

// ---------------- THE kernel: transpose -> embed -> tree -> head ----------------
__global__ void __launch_bounds__(256, 2) k_mega(
    const float* __restrict__ E_td, const float* __restrict__ E_bu,
    const float* __restrict__ td_word, const int* __restrict__ td_idx,
    const float* __restrict__ bu_word, const int* __restrict__ bu_idx,
    const float* __restrict__ Wz_td, const float* __restrict__ Wr_td, const float* __restrict__ Wh_td,
    const float* __restrict__ bz_td, const float* __restrict__ br_td, const float* __restrict__ bh_td,
    const float* __restrict__ Wz_bu, const float* __restrict__ Wr_bu, const float* __restrict__ Wh_bu,
    const float* __restrict__ bz_bu, const float* __restrict__ br_bu, const float* __restrict__ bh_bu,
    const float* __restrict__ Uz_td, const float* __restrict__ Ur_td, const float* __restrict__ Uh_td,
    const float* __restrict__ Uz_bu, const float* __restrict__ Ur_bu, const float* __restrict__ Uh_bu,
    const float* __restrict__ W1, const float* __restrict__ b1,
    const float* __restrict__ W4, const float* __restrict__ b4,
    float* __restrict__ out)
{
    extern __shared__ float sm[];
    int bid = blockIdx.x;
    int tid = threadIdx.x;

    // ============ phase 1: transpose E (H,V) -> ET (V,H) ============
    {
        float (*tile)[65] = (float (*)[65])sm;
        if (bid == 0 && tid < 64) g_h_td[tid] = 0.f;     // node_h[0] = 0
        for (int ti = bid; ti < NTT; ti += GRID) {
            const float* E = (ti < 782) ? E_td : E_bu;
            float* ET = (ti < 782) ? g_ET_td : g_ET_bu;
            int v0 = ((ti < 782) ? ti : ti - 782) * 64;
            int rem = VOCAB - v0;                         // 64 normally, 16 for last tile
            __syncthreads();
#pragma unroll
            for (int it = 0; it < 4; it++) {
                int e = it * 256 + tid;
                int h = e >> 4, c = (e & 15) * 4;
                if (c < rem) {
                    float4 v = *(const float4*)&E[(size_t)h * VOCAB + v0 + c];
                    tile[h][c] = v.x; tile[h][c + 1] = v.y;
                    tile[h][c + 2] = v.z; tile[h][c + 3] = v.w;
                }
            }
            __syncthreads();
#pragma unroll
            for (int it = 0; it < 4; it++) {
                int e = it * 256 + tid;
                int v = e >> 4, c = (e & 15) * 4;
                if (v < rem) {
                    float4 val = make_float4(tile[c][v], tile[c + 1][v], tile[c + 2][v], tile[c + 3][v]);
                    *(float4*)&ET[(size_t)(v0 + v) * 64 + c] = val;
                }
            }
        }
    }
    gbar(0, GRID, true);

    // ============ phase 2: embedding gather + gate pre-activations ============
    // static per-warp partition: warp handles 4-node groups, no block syncs in the loop
    {
        float* sW = sm;                       // 3 * 64 * WSTR
        float* sb = sW + 3 * 64 * WSTR;       // 192
        float* sWord = sb + 192;              // 32 * 64
        float* sXe = sWord + 2048;            // 32 * 64
        int* sIdx = (int*)(sXe + 2048);       // 32 * 64

        bool is_td = (bid < 148);
        const float* word = is_td ? td_word : bu_word;
        const int* idx = is_td ? td_idx : bu_idx;
        const float* ET = is_td ? g_ET_td : g_ET_bu;
        const float* Wz = is_td ? Wz_td : Wz_bu;
        const float* Wr = is_td ? Wr_td : Wr_bu;
        const float* Wh = is_td ? Wh_td : Wh_bu;
        const float* bz = is_td ? bz_td : bz_bu;
        const float* br = is_td ? br_td : br_bu;
        const float* bh = is_td ? bh_td : bh_bu;
        float* zx = is_td ? g_zx_td : g_zx_bu;
        float* rx = is_td ? g_rx_td : g_rx_bu;
        float* hx = is_td ? g_hx_td : g_hx_bu;
        int nNodes = is_td ? NTD : NBU;

        for (int g = 0; g < 3; g++) {
            const float* Wg = (g == 0) ? Wz : (g == 1) ? Wr : Wh;
            for (int e = tid; e < 4096; e += 256) {
                int hh = e >> 6, kk = e & 63;
                sW[g * 64 * WSTR + kk * WSTR + hh] = Wg[e];
            }
        }
        if (tid < 64) sb[tid] = bz[tid];
        else if (tid < 128) sb[tid] = br[tid - 64];
        else if (tid < 192) sb[tid] = bh[tid - 128];
        __syncthreads();

        int wid = tid >> 5;
        int lane = tid & 31;
        int q = lane >> 4;        // half-warp id
        int t = lane & 15;
        int h4 = t * 4;
        int gw = (is_td ? bid : bid - 148) * 8 + wid;   // global warp id within side
        const int NW = 148 * 8;                          // warps per side
        int ngroups = (nNodes + 3) >> 2;                 // 2048 per side
        int slot0 = wid * 4 + q;                         // warp-private smem slots
        int slot1 = slot0 + 2;

        for (int g = gw; g < ngroups; g += NW) {
            int base = g * 4;
            int n0 = base + q;
            int n1 = base + 2 + q;
            bool full = (base + 4 <= nNodes);
            bool a0 = full || (n0 < nNodes);
            bool a1 = full || (n1 < nNodes);
            if (a0) {
                *(int4*)&sIdx[slot0 * 64 + h4] = *(const int4*)&idx[n0 * 64 + h4];
                *(float4*)&sWord[slot0 * 64 + h4] = *(const float4*)&word[n0 * 64 + h4];
            }
            if (a1) {
                *(int4*)&sIdx[slot1 * 64 + h4] = *(const int4*)&idx[n1 * 64 + h4];
                *(float4*)&sWord[slot1 * 64 + h4] = *(const float4*)&word[n1 * 64 + h4];
            }
            __syncwarp();
            float4 acc0 = make_float4(0.f, 0.f, 0.f, 0.f);
            float4 acc1 = make_float4(0.f, 0.f, 0.f, 0.f);
            {
                const int* ip0 = &sIdx[slot0 * 64];
                const float* wp0 = &sWord[slot0 * 64];
                const int* ip1 = &sIdx[slot1 * 64];
                const float* wp1 = &sWord[slot1 * 64];
                if (full) {
#pragma unroll 4
                    for (int w = 0; w < 64; w++) {
                        float4 ea = *(const float4*)&ET[ip0[w] * 64 + h4];
                        float4 eb = *(const float4*)&ET[ip1[w] * 64 + h4];
                        float wa = wp0[w], wb = wp1[w];
                        acc0.x += ea.x * wa; acc0.y += ea.y * wa; acc0.z += ea.z * wa; acc0.w += ea.w * wa;
                        acc1.x += eb.x * wb; acc1.y += eb.y * wb; acc1.z += eb.z * wb; acc1.w += eb.w * wb;
                    }
                } else {
#pragma unroll 4
                    for (int w = 0; w < 64; w++) {
                        if (a0) {
                            float4 ea = *(const float4*)&ET[ip0[w] * 64 + h4];
                            float wa = wp0[w];
                            acc0.x += ea.x * wa; acc0.y += ea.y * wa; acc0.z += ea.z * wa; acc0.w += ea.w * wa;
                        }
                        if (a1) {
                            float4 eb = *(const float4*)&ET[ip1[w] * 64 + h4];
                            float wb = wp1[w];
                            acc1.x += eb.x * wb; acc1.y += eb.y * wb; acc1.z += eb.z * wb; acc1.w += eb.w * wb;
                        }
                    }
                }
            }
            *(float4*)&sXe[slot0 * 64 + h4] = acc0;
            *(float4*)&sXe[slot1 * 64 + h4] = acc1;
            __syncwarp();
            {
                const float* xe0 = &sXe[slot0 * 64];
                const float* xe1 = &sXe[slot1 * 64];
                float4 bzv = *(const float4*)&sb[0 * 64 + h4];
                float4 brv = *(const float4*)&sb[1 * 64 + h4];
                float4 bhv = *(const float4*)&sb[2 * 64 + h4];
                float4 az0 = bzv, ar0 = brv, ah0 = bhv;
                float4 az1 = bzv, ar1 = brv, ah1 = bhv;
#pragma unroll 4
                for (int k = 0; k < 64; k++) {
                    float4 wz4 = *(const float4*)&sW[0 * 64 * WSTR + k * WSTR + h4];
                    float4 wr4 = *(const float4*)&sW[1 * 64 * WSTR + k * WSTR + h4];
                    float4 wh4 = *(const float4*)&sW[2 * 64 * WSTR + k * WSTR + h4];
                    float x0 = xe0[k], x1 = xe1[k];
                    az0.x += wz4.x * x0; az0.y += wz4.y * x0; az0.z += wz4.z * x0; az0.w += wz4.w * x0;
                    ar0.x += wr4.x * x0; ar0.y += wr4.y * x0; ar0.z += wr4.z * x0; ar0.w += wr4.w * x0;
                    ah0.x += wh4.x * x0; ah0.y += wh4.y * x0; ah0.z += wh4.z * x0; ah0.w += wh4.w * x0;
                    az1.x += wz4.x * x1; az1.y += wz4.y * x1; az1.z += wz4.z * x1; az1.w += wz4.w * x1;
                    ar1.x += wr4.x * x1; ar1.y += wr4.y * x1; ar1.z += wr4.z * x1; ar1.w += wr4.w * x1;
                    ah1.x += wh4.x * x1; ah1.y += wh4.y * x1; ah1.z += wh4.z * x1; ah1.w += wh4.w * x1;
                }
#pragma unroll
                for (int p = 0; p < 2; p++) {
                    int n = p ? n1 : n0;
                    bool act = p ? a1 : a0;
                    float4 az = p ? az1 : az0, ar = p ? ar1 : ar0, ah = p ? ah1 : ah0;
                    if (!act) continue;
                    if (is_td || n >= LBU) {
                        *(float4*)&zx[n * 64 + h4] = az;
                        *(float4*)&rx[n * 64 + h4] = ar;
                        *(float4*)&hx[n * 64 + h4] = ah;
                    } else {
                        float4 lh;
                        lh.x = (1.f - sigmf(az.x)) * tanhf_fast(ah.x);
                        lh.y = (1.f - sigmf(az.y)) * tanhf_fast(ah.y);
                        lh.z = (1.f - sigmf(az.z)) * tanhf_fast(ah.z);
                        lh.w = (1.f - sigmf(az.w)) * tanhf_fast(ah.w);
                        *(float4*)&g_h_bu[n * 64 + h4] = lh;
                    }
                }
            }
            // no trailing sync needed: next iteration's writes are separated from this
            // iteration's reads by the two __syncwarp()s above (lockstep per warp)
        }
    }
    gbar(1, GRID, true);

    // ============ phase 3: tree recurrences + head (ALL 296 blocks) ============
    {
        float* sU = sm;                       // 3 * 64 * WSTR
        float* sHp = sU + 3 * 64 * WSTR;      // 16 * 64
        float* sHr = sHp + 1024;              // 16 * 64

        bool is_td = (bid < TDB);
        int gid = is_td ? bid : bid - TDB;

        const float* Uz = is_td ? Uz_td : Uz_bu;
        const float* Ur = is_td ? Ur_td : Ur_bu;
        const float* Uh = is_td ? Uh_td : Uh_bu;
        const float* gz = is_td ? g_zx_td : g_zx_bu;
        const float* gr = is_td ? g_rx_td : g_rx_bu;
        const float* gh = is_td ? g_hx_td : g_hx_bu;

        for (int g = 0; g < 3; g++) {
            const float* Ug = (g == 0) ? Uz : (g == 1) ? Ur : Uh;
            for (int e = tid; e < 4096; e += 256) {
                int hh = e >> 6, kk = e & 63;
                sU[g * 64 * WSTR + kk * WSTR + hh] = Ug[e];
            }
        }
        if (bid == 0) {
            // prefetch head weights into L2 (used ~tree-latency later)
            asm volatile("prefetch.global.L2 [%0];" :: "l"(&W1[tid * 32]));
            if (tid < 8) asm volatile("prefetch.global.L2 [%0];" :: "l"(&W4[tid * 32]));
        }
        __syncthreads();

        int slot = tid >> 4;
        int t = tid & 15;
        int h4 = t * 4;
        const float4 f40 = make_float4(0.f, 0.f, 0.f, 0.f);

        if (is_td) {
            // levels 1..4 (1 tile each): solo by block 0; syncthreads between levels (cross-warp dep)
            if (gid == 0) {
                for (int s = 1; s <= 4; s++) {
                    int lo = (1 << s) - 1, cnt = 1 << s;
                    gru_tile(true, lo, cnt, 0, gz, gr, gh, sU, sHp, sHr, slot, h4, false, f40, f40, f40);
                    __syncthreads();
                }
            }
            // prefetch level-5 gates (cnt=32, lo=31)
            float4 paz = f40, par = f40, pah = f40;
            bool useP = false;
            {
                int r = gid * 16 + slot;
                if (r < 32) {
                    int gi = 30 + r;
                    paz = *(const float4*)&gz[gi * 64 + h4];
                    par = *(const float4*)&gr[gi * 64 + h4];
                    pah = *(const float4*)&gh[gi * 64 + h4];
                    useP = true;
                }
            }
            gbar(2, TDB, true);
            // levels 5..13: TDB blocks, per-level barrier, gate prefetch across barrier
            for (int s = 5; s <= 13; s++) {
                int lo = (1 << s) - 1;
                int cnt = (s < 13) ? (1 << s) : 2;
                int tiles = (cnt + 15) >> 4;
                for (int tile = gid; tile < tiles; tile += TDB)
                    gru_tile(true, lo, cnt, tile, gz, gr, gh, sU, sHp, sHr, slot, h4,
                             (tile == gid) && useP, paz, par, pah);
                useP = false;
                if (s < 13) {
                    int s2 = s + 1;
                    int lo2 = (1 << s2) - 1;
                    int cnt2 = (s2 < 13) ? (1 << s2) : 2;
                    int r = gid * 16 + slot;
                    if (r < cnt2) {
                        int gi = lo2 + r - 1;
                        paz = *(const float4*)&gz[gi * 64 + h4];
                        par = *(const float4*)&gr[gi * 64 + h4];
                        pah = *(const float4*)&gh[gi * 64 + h4];
                        useP = true;
                    }
                }
                gbar(3 + s - 5, TDB, true);       // indices 3..11
            }
            // partial max over leaf rows 4096..8192 (first 64 td blocks)
            if (gid < 64 && tid < 64) {
                int h = tid;
                float m = -1e30f;
                for (int r = 4096 + gid; r <= NTD; r += 64)
                    m = fmaxf(m, g_h_td[r * 64 + h]);
                g_tdmax[gid * 64 + h] = m;
            }
            // head barrier: TDB td blocks + bu root block = TDB+1; only td block 0 waits
            gbar(12, TDB + 1, gid == 0);

            if (gid == 0) {
                __shared__ float fs[128], f1[64], lg[4];
                if (tid < 64) {
                    float m = -1e30f;
#pragma unroll 8
                    for (int b = 0; b < 64; b++) m = fmaxf(m, g_tdmax[b * 64 + tid]);
                    fs[tid] = m;
                } else if (tid < 128) {
                    fs[tid] = g_h_bu[(NBU - 1) * 64 + (tid - 64)];
                }
                __syncthreads();
                {
                    int row = tid >> 2, part = tid & 3;
                    float s = 0.f;
#pragma unroll
                    for (int i = 0; i < 8; i++) {
                        int k = part * 32 + i * 4;
                        float4 w = *(const float4*)&W1[row * 128 + k];
                        s += w.x * fs[k] + w.y * fs[k + 1] + w.z * fs[k + 2] + w.w * fs[k + 3];
                    }
                    s += __shfl_down_sync(0xffffffffu, s, 1);
                    s += __shfl_down_sync(0xffffffffu, s, 2);
                    if (part == 0) f1[row] = fmaxf(s + b1[row], 0.f);
                }
                __syncthreads();
                if (tid < 128) {
                    int row = tid >> 5, lane = tid & 31;
                    float s = W4[row * 64 + lane] * f1[lane] + W4[row * 64 + 32 + lane] * f1[32 + lane];
#pragma unroll
                    for (int o = 16; o > 0; o >>= 1) s += __shfl_down_sync(0xffffffffu, s, o);
                    if (lane == 0) lg[row] = s + b4[row];
                }
                __syncthreads();
                if (tid == 0) {
                    float mx = fmaxf(fmaxf(lg[0], lg[1]), fmaxf(lg[2], lg[3]));
                    float e0 = expf(lg[0] - mx), e1 = expf(lg[1] - mx);
                    float e2 = expf(lg[2] - mx), e3 = expf(lg[3] - mx);
                    float sI = e0 + e1 + e2 + e3;
                    out[0] = e0 / sI; out[1] = e1 / sI; out[2] = e2 / sI; out[3] = e3 / sI;
                }
            }
        } else {
            // bu levels 1..7 (2048..32 nodes): BUB blocks, per-level barrier + prefetch
            float4 paz = f40, par = f40, pah = f40;
            bool useP = false;
            {
                int r = gid * 16 + slot;          // level 1: lo=0, cnt=2048
                if (r < 2048) {
                    int gi = LBU + r;
                    paz = *(const float4*)&gz[gi * 64 + h4];
                    par = *(const float4*)&gr[gi * 64 + h4];
                    pah = *(const float4*)&gh[gi * 64 + h4];
                    useP = true;
                }
            }
            for (int s = 1; s <= 7; s++) {
                int cnt = 1 << (12 - s);
                int lo = 4096 - (1 << (13 - s));
                int tiles = cnt >> 4;
                for (int tile = gid; tile < tiles; tile += BUB)
                    gru_tile(false, lo, cnt, tile, gz, gr, gh, sU, sHp, sHr, slot, h4,
                             (tile == gid) && useP, paz, par, pah);
                useP = false;
                {
                    int s2 = s + 1;
                    int cnt2 = 1 << (12 - s2);
                    int lo2 = 4096 - (1 << (13 - s2));
                    int r = gid * 16 + slot;
                    if (r < cnt2) {
                        int gi = LBU + lo2 + r;
                        paz = *(const float4*)&gz[gi * 64 + h4];
                        par = *(const float4*)&gr[gi * 64 + h4];
                        pah = *(const float4*)&gh[gi * 64 + h4];
                        useP = true;
                    }
                }
                gbar(13 + s - 1, BUB, true);      // indices 13..19
            }
            // levels 8..12 (16..1 nodes): solo by bu block 0; syncthreads between levels
            if (gid == 0) {
                for (int s = 8; s <= 12; s++) {
                    int cnt = 1 << (12 - s);
                    int lo = 4096 - (1 << (13 - s));
                    gru_tile(false, lo, cnt, 0, gz, gr, gh, sU, sHp, sHr, slot, h4,
                             (s == 8) && useP, paz, par, pah);
                    __syncthreads();
                }
                gbar(12, TDB + 1, false);   // arrive at head barrier (publishes bu root)
            }
        }
    }

    // ============ final barrier + counter reset ============
    gbar(20, GRID, bid == 0);
    if (bid == 0 && tid < 32) g_ctr[tid * 8] = 0;
}

// ---------------- launch ----------------
extern "C" void kernel_launch(void* const* d_in, const int* in_sizes, int n_in,
                              void* d_out, int out_size) {
    const float* td_x_word = (const float*)d_in[0];
    const float* bu_x_word = (const float*)d_in[1];
    const float* E_td  = (const float*)d_in[2];
    const float* Wz_td = (const float*)d_in[3];
    const float* Uz_td = (const float*)d_in[4];
    const float* bz_td = (const float*)d_in[5];
    const float* Wr_td = (const float*)d_in[6];
    const float* Ur_td = (const float*)d_in[7];
    const float* br_td = (const float*)d_in[8];
    const float* Wh_td = (const float*)d_in[9];
    const float* Uh_td = (const float*)d_in[10];
    const float* bh_td = (const float*)d_in[11];
    const float* E_bu  = (const float*)d_in[12];
    const float* Wz_bu = (const float*)d_in[13];
    const float* Uz_bu = (const float*)d_in[14];
    const float* bz_bu = (const float*)d_in[15];
    const float* Wr_bu = (const float*)d_in[16];
    const float* Ur_bu = (const float*)d_in[17];
    const float* br_bu = (const float*)d_in[18];
    const float* Wh_bu = (const float*)d_in[19];
    const float* Uh_bu = (const float*)d_in[20];
    const float* bh_bu = (const float*)d_in[21];
    const float* W1 = (const float*)d_in[22];
    const float* b1 = (const float*)d_in[23];
    const float* W4 = (const float*)d_in[24];
    const float* b4 = (const float*)d_in[25];

    const int* idx_td = (const int*)d_in[26];
    const int* idx_bu = (const int*)d_in[27];
    for (int i = 26; i < n_in; i++) {
        if (in_sizes[i] == NTD * 64) idx_td = (const int*)d_in[i];
        else if (in_sizes[i] == NBU * 64) idx_bu = (const int*)d_in[i];
    }

    const int smemM = (3 * 64 * WSTR + 192 + 2048 + 2048 + 2048) * 4;   // 77568 B
    cudaFuncSetAttribute(k_mega, cudaFuncAttributeMaxDynamicSharedMemorySize, smemM);

    k_mega<<<GRID, 256, smemM>>>(
        E_td, E_bu, td_x_word, idx_td, bu_x_word, idx_bu,
        Wz_td, Wr_td, Wh_td, bz_td, br_td, bh_td,
        Wz_bu, Wr_bu, Wh_bu, bz_bu, br_bu, bh_bu,
        Uz_td, Ur_td, Uh_td, Uz_bu, Ur_bu, Uh_bu,
        W1, b1, W4, b4, (float*)d_out);
}